// round 6
// baseline (speedup 1.0000x reference)
#include <cuda_runtime.h>
#include <cstdint>
#include <cstddef>

// ============================================================================
// Compile-time basis construction
// ============================================================================
__host__ __device__ constexpr double cexp_(double v) {
    double t = 1.0, s = 1.0;
    for (int n = 1; n < 90; ++n) { t *= v / n; s += t; }
    return s;
}
__host__ __device__ constexpr double csqrt_(double v) {
    if (v <= 0.0) return 0.0;
    double x = v < 1.0 ? 1.0 : v;
    for (int i = 0; i < 80; ++i) x = 0.5 * (x + v / x);
    return x;
}

struct Basis {
    float b0[3][5][5];
    float br[3][2][5][5];
    float bi[3][2][5][5];
};

__host__ __device__ constexpr Basis make_basis() {
    Basis B{};
    for (int yy = 0; yy < 5; ++yy) {
        for (int xx = 0; xx < 5; ++xx) {
            double ys = yy - 2.0, xs = xx - 2.0;
            double r = csqrt_(ys * ys + xs * xs);
            double cth = r > 0.0 ? xs / r : 1.0;
            double sth = r > 0.0 ? ys / r : 0.0;
            double ring0 = cexp_(-(r - 0.0) * (r - 0.0) / 0.72);
            double ring1 = cexp_(-(r - 1.0) * (r - 1.0) / 0.72);
            double ring2 = cexp_(-(r - 2.0) * (r - 2.0) / 0.72);
            B.b0[0][yy][xx] = (float)ring0;
            B.b0[1][yy][xx] = (float)ring1;
            B.b0[2][yy][xx] = (float)ring2;
            double ck = cth, sk = sth;
            for (int k = 0; k < 3; ++k) {
                B.br[k][0][yy][xx] = (float)(ring1 * ck);
                B.br[k][1][yy][xx] = (float)(ring2 * ck);
                B.bi[k][0][yy][xx] = (float)(ring1 * sk);
                B.bi[k][1][yy][xx] = (float)(ring2 * sk);
                double cn = ck * cth - sk * sth;
                double sn = sk * cth + ck * sth;
                ck = cn; sk = sn;
            }
        }
    }
    return B;
}

// ============================================================================
// Intermediate
// ============================================================================
__device__ float g_y[(size_t)8 * 144 * 192 * 192];

// ============================================================================
// Pass 1: y[n, o*9+c, p] = sum_i w[o,i,c] * x[n,i,p]
// Weights staged in smem PRE-SPLATTED as 64-bit {w,w} pairs, pitch 34 ->
// inner loop: 1 LDS.128 (2 splatted w) + 4 fma.rn.f32x2 per (c, i-pair).
// 256 thr = 16 o x 16 px-groups (4 px), 4 CTA/SM.
// ============================================================================
#define FMA2(acc, a, b) \
    asm("fma.rn.f32x2 %0, %1, %2, %0;" : "+l"(acc) : "l"(a), "l"(b))
#define SPLAT2(dst, f) \
    asm("mov.b64 %0, {%1, %1};" : "=l"(dst) : "f"(f))

__global__ __launch_bounds__(256, 4) void pass1(const float* __restrict__ x,
                                                const float* __restrict__ wts) {
    __shared__ float xs[32 * 64];                      // 8 KB
    __shared__ unsigned long long ws2[144 * 34];       // 38.25 KB, [(o*9+c)*34+i]
    const int n = blockIdx.y;
    const int p0 = blockIdx.x * 64;
    const int tid = threadIdx.x;

    // transpose + splat weights: (o,i,c) -> [(o,c)][i] as {w,w}
    for (int e = tid; e < 4608; e += 256) {
        int o = e / 288, r = e % 288, i = r / 9, c = r % 9;
        unsigned long long w2;
        SPLAT2(w2, wts[e]);
        ws2[(o * 9 + c) * 34 + i] = w2;
    }
    const float* xb = x + (size_t)n * 32 * 36864 + p0;
    for (int e = tid; e < 512; e += 256) {
        int i = e >> 4, p4 = e & 15;
        *(float4*)(xs + i * 64 + p4 * 4) =
            *(const float4*)(xb + (size_t)i * 36864 + p4 * 4);
    }
    __syncthreads();

    const int o  = tid & 15;
    const int pg = tid >> 4;   // 4 px each

    unsigned long long acc2[9][2];
#pragma unroll
    for (int c = 0; c < 9; ++c) { acc2[c][0] = 0ULL; acc2[c][1] = 0ULL; }

    const float* xg = xs + pg * 4;
    const unsigned long long* wg = ws2 + o * 306;   // 9*34

#pragma unroll 4
    for (int i2 = 0; i2 < 32; i2 += 2) {
        longlong2 xa = *(const longlong2*)(xg + i2 * 64);
        longlong2 xc = *(const longlong2*)(xg + (i2 + 1) * 64);
        unsigned long long x0 = (unsigned long long)xa.x;
        unsigned long long x1 = (unsigned long long)xa.y;
        unsigned long long x2 = (unsigned long long)xc.x;
        unsigned long long x3 = (unsigned long long)xc.y;
#pragma unroll
        for (int c = 0; c < 9; ++c) {
            ulonglong2 w2 = *(const ulonglong2*)(wg + c * 34 + i2);
            FMA2(acc2[c][0], w2.x, x0);
            FMA2(acc2[c][1], w2.x, x1);
            FMA2(acc2[c][0], w2.y, x2);
            FMA2(acc2[c][1], w2.y, x3);
        }
    }

    size_t base = ((size_t)n * 144 + o * 9) * 36864 + p0 + pg * 4;
#pragma unroll
    for (int c = 0; c < 9; ++c) {
        longlong2 s;
        s.x = (long long)acc2[c][0];
        s.y = (long long)acc2[c][1];
        *(longlong2*)(g_y + base + (size_t)c * 36864) = s;
    }
}

// ============================================================================
// Pass 2: 2x4 outputs per thread. smem tile [72][18][20] (even pitch ->
// aligned LDS.64 on window rows). 512 thr = 128 positions x 4 o-subgroups,
// each handling 2 o sequentially. 2 CTA/SM.
// ============================================================================
__device__ __forceinline__ float dotT4(const float (&T)[5][5],
                                       const float (&w)[3][4],
                                       int SY, int SX, int ox) {
    float s = 0.f;
#pragma unroll
    for (int dy = 0; dy < 3; ++dy) {
        if (dy < SY) continue;
        int vy = (SY ? 5 : 4) - 2 * dy;
#pragma unroll
        for (int dx = 0; dx < 3; ++dx) {
            if (dx < SX) continue;
            int vx = (SX ? 5 : 4) - 2 * dx;
            float cf = T[vy][vx];
            if (cf != 0.f) s += cf * w[dy][ox + dx];
        }
    }
    return s;
}

__global__ __launch_bounds__(512, 2) void pass2(const float* __restrict__ alpha,
                                                const float* __restrict__ bias,
                                                float* __restrict__ out) {
    constexpr Basis BAS = make_basis();
    extern __shared__ float ysm[];   // [72][18][20]

    const int tx = blockIdx.x, ty = blockIdx.y;
    const int n  = blockIdx.z >> 1;
    const int oh = blockIdx.z & 1;
    const int tid = threadIdx.x;
    const int ix0 = tx * 16, iy0 = ty * 16;

    const float* yg = g_y + ((size_t)n * 144 + oh * 72) * 36864;
    const bool interior = (tx > 0) & (tx < 11) & (ty > 0) & (ty < 11);
    if (interior) {
        for (int e = tid; e < 72 * 324; e += 512) {
            int oc = e / 324;
            int rem = e - oc * 324;
            int r = rem / 18;
            int cc = rem - r * 18;
            ysm[(oc * 18 + r) * 20 + cc] =
                yg[(size_t)oc * 36864 + (iy0 - 1 + r) * 192 + (ix0 - 1 + cc)];
        }
    } else {
        for (int e = tid; e < 72 * 324; e += 512) {
            int oc = e / 324;
            int rem = e - oc * 324;
            int r = rem / 18;
            int cc = rem - r * 18;
            int gy = iy0 - 1 + r, gx = ix0 - 1 + cc;
            float v = 0.f;
            if ((unsigned)gy < 192u && (unsigned)gx < 192u)
                v = yg[(size_t)oc * 36864 + gy * 192 + gx];
            ysm[(oc * 18 + r) * 20 + cc] = v;
        }
    }
    __syncthreads();

    const int pos = tid & 127;     // 16 (y) x 8 (x) positions of 2x4 px
    const int os  = tid >> 7;      // 0..3, 2 o each
    const int posy = pos >> 3, posx = pos & 7;
    const int py0 = ty * 32 + 2 * posy;
    const int px0 = tx * 32 + 4 * posx;

    // Modulation for 8 px: rho + first-harmonic direction
    float RHO[2][4], C1[2][4], S1[2][4];
    {
        const float* ab = alpha + (size_t)n * 147456 + (size_t)py0 * 384 + px0;
#pragma unroll
        for (int sy = 0; sy < 2; ++sy) {
            float4 a0 = *(const float4*)(ab + sy * 384);
            float4 a1 = *(const float4*)(ab + sy * 384 + (size_t)8 * 147456);
            float a0v[4] = {a0.x, a0.y, a0.z, a0.w};
            float a1v[4] = {a1.x, a1.y, a1.z, a1.w};
#pragma unroll
            for (int j = 0; j < 4; ++j) {
                float rho = sqrtf(a0v[j] * a0v[j] + a1v[j] * a1v[j]);
                float inv = 1.0f / (rho + 1e-8f);
                RHO[sy][j] = rho;
                C1[sy][j] = a0v[j] * inv;
                S1[sy][j] = a1v[j] * inv;
            }
        }
    }

#pragma unroll
    for (int oi = 0; oi < 2; ++oi) {
        const int ol = os * 2 + oi;
        const int o  = oh * 8 + ol;
        float acc[2][4] = {{0.f, 0.f, 0.f, 0.f}, {0.f, 0.f, 0.f, 0.f}};
        float ck[2][4], sk[2][4];
#pragma unroll
        for (int sy = 0; sy < 2; ++sy)
#pragma unroll
            for (int j = 0; j < 4; ++j) { ck[sy][j] = C1[sy][j]; sk[sy][j] = S1[sy][j]; }

#pragma unroll
        for (int c = 0; c < 9; ++c) {
            if (c == 5 || c == 7) {
#pragma unroll
                for (int sy = 0; sy < 2; ++sy)
#pragma unroll
                    for (int j = 0; j < 4; ++j) {
                        float cn = ck[sy][j] * C1[sy][j] - sk[sy][j] * S1[sy][j];
                        float sn = sk[sy][j] * C1[sy][j] + ck[sy][j] * S1[sy][j];
                        ck[sy][j] = cn; sk[sy][j] = sn;
                    }
            }
            // 3x4 window, rows loaded as 2 aligned float2
            const float* wbp = ysm + ((ol * 9 + c) * 18 + posy) * 20 + posx * 2;
            float w[3][4];
#pragma unroll
            for (int dy = 0; dy < 3; ++dy) {
                float2 lo = *(const float2*)(wbp + dy * 20);
                float2 hi = *(const float2*)(wbp + dy * 20 + 2);
                w[dy][0] = lo.x; w[dy][1] = lo.y; w[dy][2] = hi.x; w[dy][3] = hi.y;
            }

            if (c < 3) {
#pragma unroll
                for (int sy = 0; sy < 2; ++sy)
#pragma unroll
                    for (int sxi = 0; sxi < 4; ++sxi)
                        acc[sy][sxi] += dotT4(BAS.b0[c], w, sy, sxi & 1, sxi >> 1);
            } else {
                const int k = (c - 3) >> 1;
                const int j = (c - 3) & 1;
#pragma unroll
                for (int sy = 0; sy < 2; ++sy)
#pragma unroll
                    for (int sxi = 0; sxi < 4; ++sxi) {
                        float dR = dotT4(BAS.br[k][j], w, sy, sxi & 1, sxi >> 1);
                        float dI = dotT4(BAS.bi[k][j], w, sy, sxi & 1, sxi >> 1);
                        acc[sy][sxi] += dR * ck[sy][sxi] + dI * sk[sy][sxi];
                    }
            }
        }
        float bo = bias[o];
        float* ob = out + ((size_t)(n * 16 + o)) * 147456 + (size_t)py0 * 384 + px0;
#pragma unroll
        for (int sy = 0; sy < 2; ++sy) {
            float4 v;
            v.x = RHO[sy][0] * acc[sy][0] + bo;
            v.y = RHO[sy][1] * acc[sy][1] + bo;
            v.z = RHO[sy][2] * acc[sy][2] + bo;
            v.w = RHO[sy][3] * acc[sy][3] + bo;
            *(float4*)(ob + sy * 384) = v;
        }
    }
}

// ============================================================================
// Launch
// ============================================================================
extern "C" void kernel_launch(void* const* d_in, const int* in_sizes, int n_in,
                              void* d_out, int out_size) {
    const float* x     = (const float*)d_in[0];  // (8,32,192,192)
    const float* alpha = (const float*)d_in[1];  // (2,8,1,384,384)
    const float* wts   = (const float*)d_in[2];  // (16,32,9)
    const float* bias  = (const float*)d_in[3];  // (16,)
    float* out = (float*)d_out;                  // (8,16,384,384)

    (void)in_sizes; (void)n_in; (void)out_size;

    const int smem2 = 72 * 18 * 20 * 4;  // 103680 bytes
    cudaFuncSetAttribute(pass2, cudaFuncAttributeMaxDynamicSharedMemorySize, smem2);

    pass1<<<dim3(576, 8), 256>>>(x, wts);
    pass2<<<dim3(12, 12, 16), 512, smem2>>>(alpha, bias, out);
}

// round 7
// speedup vs baseline: 1.1783x; 1.1783x over previous
#include <cuda_runtime.h>
#include <cstdint>
#include <cstddef>

// ============================================================================
// Compile-time basis construction
// ============================================================================
__host__ __device__ constexpr double cexp_(double v) {
    double t = 1.0, s = 1.0;
    for (int n = 1; n < 90; ++n) { t *= v / n; s += t; }
    return s;
}
__host__ __device__ constexpr double csqrt_(double v) {
    if (v <= 0.0) return 0.0;
    double x = v < 1.0 ? 1.0 : v;
    for (int i = 0; i < 80; ++i) x = 0.5 * (x + v / x);
    return x;
}

struct Basis {
    float b0[3][5][5];
    float br[3][2][5][5];
    float bi[3][2][5][5];
};

__host__ __device__ constexpr Basis make_basis() {
    Basis B{};
    for (int yy = 0; yy < 5; ++yy) {
        for (int xx = 0; xx < 5; ++xx) {
            double ys = yy - 2.0, xs = xx - 2.0;
            double r = csqrt_(ys * ys + xs * xs);
            double cth = r > 0.0 ? xs / r : 1.0;
            double sth = r > 0.0 ? ys / r : 0.0;
            double ring0 = cexp_(-(r - 0.0) * (r - 0.0) / 0.72);
            double ring1 = cexp_(-(r - 1.0) * (r - 1.0) / 0.72);
            double ring2 = cexp_(-(r - 2.0) * (r - 2.0) / 0.72);
            B.b0[0][yy][xx] = (float)ring0;
            B.b0[1][yy][xx] = (float)ring1;
            B.b0[2][yy][xx] = (float)ring2;
            double ck = cth, sk = sth;
            for (int k = 0; k < 3; ++k) {
                B.br[k][0][yy][xx] = (float)(ring1 * ck);
                B.br[k][1][yy][xx] = (float)(ring2 * ck);
                B.bi[k][0][yy][xx] = (float)(ring1 * sk);
                B.bi[k][1][yy][xx] = (float)(ring2 * sk);
                double cn = ck * cth - sk * sth;
                double sn = sk * cth + ck * sth;
                ck = cn; sk = sn;
            }
        }
    }
    return B;
}

// ============================================================================
// Globals
// ============================================================================
__device__ float g_y[(size_t)8 * 144 * 192 * 192];
__device__ float g_wt2[16 * 322];   // [o*322 + i*10 + c], c in 0..9 (c=9 zero)

// ============================================================================
// Pass 0: transpose weights (o,i,c) -> [o][i][c-padded-10], zero pad c=9
// ============================================================================
__global__ void wtrans(const float* __restrict__ wts) {
    int e = blockIdx.x * 512 + threadIdx.x;   // 10 blocks x 512 = 5120
    if (e >= 5120) return;
    int o = e / 320, r = e % 320, i = r / 10, c = r % 10;
    float v = (c < 9) ? wts[o * 288 + i * 9 + c] : 0.f;
    g_wt2[o * 322 + i * 10 + c] = v;
}

// ============================================================================
// Pass 1: y[n, o*9+c, p] = sum_i w[o,i,c] * x[n,i,p]
// Channel-pair packed accumulators: acc = {acc_c, acc_c+1} per pixel.
// Weight operand = contiguous {w_c, w_c+1} -> 1 LDS.64, no splat.
// x pre-splatted in smem as {x,x} u64 -> LDS.128 gives 2 pixels.
// Per i: 2 LDS.128 + 5 LDS.64 + 20 FMA2.
// 256 thr = 16 o x 16 px-groups (4 px), 4 CTA/SM.
// ============================================================================
#define FMA2(acc, a, b) \
    asm("fma.rn.f32x2 %0, %1, %2, %0;" : "+l"(acc) : "l"(a), "l"(b))
#define SPLAT2(dst, f) \
    asm("mov.b64 %0, {%1, %1};" : "=l"(dst) : "f"(f))

__global__ __launch_bounds__(256, 4) void pass1(const float* __restrict__ x) {
    __shared__ unsigned long long xs2[32 * 64];   // [i][px] splatted, 16 KB
    __shared__ float ws[16 * 322];                // [o][i][10], 20.6 KB
    const int n = blockIdx.y;
    const int p0 = blockIdx.x * 64;
    const int tid = threadIdx.x;

    for (int e = tid; e < 5152; e += 256) ws[e] = g_wt2[e];

    const float* xb = x + (size_t)n * 32 * 36864 + p0;
    for (int e = tid; e < 512; e += 256) {
        int i = e >> 4, p4 = e & 15;
        float4 f = *(const float4*)(xb + (size_t)i * 36864 + p4 * 4);
        unsigned long long s0, s1, s2, s3;
        SPLAT2(s0, f.x); SPLAT2(s1, f.y); SPLAT2(s2, f.z); SPLAT2(s3, f.w);
        xs2[i * 64 + p4 * 4 + 0] = s0;
        xs2[i * 64 + p4 * 4 + 1] = s1;
        xs2[i * 64 + p4 * 4 + 2] = s2;
        xs2[i * 64 + p4 * 4 + 3] = s3;
    }
    __syncthreads();

    const int o  = tid & 15;
    const int pg = tid >> 4;   // 4 px each

    unsigned long long acc2[5][4];   // [c-pair][px]
#pragma unroll
    for (int p = 0; p < 5; ++p)
#pragma unroll
        for (int j = 0; j < 4; ++j) acc2[p][j] = 0ULL;

    const unsigned long long* xg = xs2 + pg * 4;
    const float* wg = ws + o * 322;

#pragma unroll 8
    for (int i = 0; i < 32; ++i) {
        ulonglong2 xa = *(const ulonglong2*)(xg + i * 64);
        ulonglong2 xb2 = *(const ulonglong2*)(xg + i * 64 + 2);
        unsigned long long xv[4] = {xa.x, xa.y, xb2.x, xb2.y};
#pragma unroll
        for (int p = 0; p < 5; ++p) {
            unsigned long long w2 = *(const unsigned long long*)(wg + i * 10 + p * 2);
#pragma unroll
            for (int j = 0; j < 4; ++j) FMA2(acc2[p][j], w2, xv[j]);
        }
    }

    size_t base = ((size_t)n * 144 + o * 9) * 36864 + p0 + pg * 4;
#pragma unroll
    for (int p = 0; p < 5; ++p) {
        float lo[4], hi[4];
#pragma unroll
        for (int j = 0; j < 4; ++j) {
            uint2 u = *(uint2*)&acc2[p][j];
            lo[j] = __uint_as_float(u.x);
            hi[j] = __uint_as_float(u.y);
        }
        *(float4*)(g_y + base + (size_t)(2 * p) * 36864) =
            make_float4(lo[0], lo[1], lo[2], lo[3]);
        if (p < 4)
            *(float4*)(g_y + base + (size_t)(2 * p + 1) * 36864) =
                make_float4(hi[0], hi[1], hi[2], hi[3]);
    }
}

// ============================================================================
// Pass 2 (exact R5): quad outputs, 72-channel smem split, rolling Chebyshev.
// ============================================================================
__device__ __forceinline__ float dotT(const float (&T)[5][5],
                                      const float (&w)[3][3],
                                      int SY, int SX) {
    float s = 0.f;
#pragma unroll
    for (int dy = 0; dy < 3; ++dy) {
        if (dy < SY) continue;
        int vy = (SY ? 5 : 4) - 2 * dy;
#pragma unroll
        for (int dx = 0; dx < 3; ++dx) {
            if (dx < SX) continue;
            int vx = (SX ? 5 : 4) - 2 * dx;
            float cf = T[vy][vx];
            if (cf != 0.f) s += cf * w[dy][dx];
        }
    }
    return s;
}

__global__ __launch_bounds__(512, 2) void pass2(const float* __restrict__ alpha,
                                                const float* __restrict__ bias,
                                                float* __restrict__ out) {
    constexpr Basis BAS = make_basis();
    extern __shared__ float ysm[];   // [72][18][19]

    const int tx = blockIdx.x, ty = blockIdx.y;
    const int n  = blockIdx.z >> 1;
    const int oh = blockIdx.z & 1;
    const int tid = threadIdx.x;
    const int ix0 = tx * 16, iy0 = ty * 16;

    const float* yg = g_y + ((size_t)n * 144 + oh * 72) * 36864;
    const bool interior = (tx > 0) & (tx < 11) & (ty > 0) & (ty < 11);
    if (interior) {
        for (int e = tid; e < 72 * 324; e += 512) {
            int oc = e / 324;
            int rem = e - oc * 324;
            int r = rem / 18;
            int cc = rem - r * 18;
            ysm[(oc * 18 + r) * 19 + cc] =
                yg[(size_t)oc * 36864 + (iy0 - 1 + r) * 192 + (ix0 - 1 + cc)];
        }
    } else {
        for (int e = tid; e < 72 * 324; e += 512) {
            int oc = e / 324;
            int rem = e - oc * 324;
            int r = rem / 18;
            int cc = rem - r * 18;
            int gy = iy0 - 1 + r, gx = ix0 - 1 + cc;
            float v = 0.f;
            if ((unsigned)gy < 192u && (unsigned)gx < 192u)
                v = yg[(size_t)oc * 36864 + gy * 192 + gx];
            ysm[(oc * 18 + r) * 19 + cc] = v;
        }
    }
    __syncthreads();

    const int q  = tid & 255;
    const int os = tid >> 8;       // 4 o each
    const int qy = q >> 4, qx = q & 15;
    const int py0 = ty * 32 + 2 * qy;
    const int px0 = tx * 32 + 2 * qx;

    float C1[2][2], S1[2][2], RHO[2][2];
    {
        const float* a0p = alpha + (size_t)n * 147456 + (size_t)py0 * 384 + px0;
        const float* a1p = a0p + (size_t)8 * 147456;
#pragma unroll
        for (int sy = 0; sy < 2; ++sy)
#pragma unroll
            for (int sx = 0; sx < 2; ++sx) {
                float a0 = a0p[sy * 384 + sx];
                float a1 = a1p[sy * 384 + sx];
                float rho = sqrtf(a0 * a0 + a1 * a1);
                float inv = 1.0f / (rho + 1e-8f);
                RHO[sy][sx] = rho;
                C1[sy][sx] = a0 * inv;
                S1[sy][sx] = a1 * inv;
            }
    }

    for (int ol = os * 4; ol < os * 4 + 4; ++ol) {
        const int o = oh * 8 + ol;
        float acc[2][2] = {{0.f, 0.f}, {0.f, 0.f}};
        float ck[2][2], sk[2][2];
#pragma unroll
        for (int sy = 0; sy < 2; ++sy)
#pragma unroll
            for (int sx = 0; sx < 2; ++sx) { ck[sy][sx] = C1[sy][sx]; sk[sy][sx] = S1[sy][sx]; }

#pragma unroll
        for (int c = 0; c < 9; ++c) {
            if (c == 5 || c == 7) {
#pragma unroll
                for (int sy = 0; sy < 2; ++sy)
#pragma unroll
                    for (int sx = 0; sx < 2; ++sx) {
                        float cn = ck[sy][sx] * C1[sy][sx] - sk[sy][sx] * S1[sy][sx];
                        float sn = sk[sy][sx] * C1[sy][sx] + ck[sy][sx] * S1[sy][sx];
                        ck[sy][sx] = cn; sk[sy][sx] = sn;
                    }
            }
            const float* wbp = ysm + ((ol * 9 + c) * 18 + qy) * 19 + qx;
            float w[3][3];
#pragma unroll
            for (int dy = 0; dy < 3; ++dy)
#pragma unroll
                for (int dx = 0; dx < 3; ++dx) w[dy][dx] = wbp[dy * 19 + dx];

            if (c < 3) {
                acc[0][0] += dotT(BAS.b0[c], w, 0, 0);
                acc[0][1] += dotT(BAS.b0[c], w, 0, 1);
                acc[1][0] += dotT(BAS.b0[c], w, 1, 0);
                acc[1][1] += dotT(BAS.b0[c], w, 1, 1);
            } else {
                const int k = (c - 3) >> 1;
                const int j = (c - 3) & 1;
#pragma unroll
                for (int sy = 0; sy < 2; ++sy)
#pragma unroll
                    for (int sx = 0; sx < 2; ++sx) {
                        float dR = dotT(BAS.br[k][j], w, sy, sx);
                        float dI = dotT(BAS.bi[k][j], w, sy, sx);
                        acc[sy][sx] += dR * ck[sy][sx] + dI * sk[sy][sx];
                    }
            }
        }
        float bo = bias[o];
#pragma unroll
        for (int sy = 0; sy < 2; ++sy) {
            float2 v;
            v.x = RHO[sy][0] * acc[sy][0] + bo;
            v.y = RHO[sy][1] * acc[sy][1] + bo;
            *(float2*)(out + ((size_t)(n * 16 + o)) * 147456 +
                       (size_t)(py0 + sy) * 384 + px0) = v;
        }
    }
}

// ============================================================================
// Launch
// ============================================================================
extern "C" void kernel_launch(void* const* d_in, const int* in_sizes, int n_in,
                              void* d_out, int out_size) {
    const float* x     = (const float*)d_in[0];  // (8,32,192,192)
    const float* alpha = (const float*)d_in[1];  // (2,8,1,384,384)
    const float* wts   = (const float*)d_in[2];  // (16,32,9)
    const float* bias  = (const float*)d_in[3];  // (16,)
    float* out = (float*)d_out;                  // (8,16,384,384)

    (void)in_sizes; (void)n_in; (void)out_size;

    const int smem2 = 72 * 18 * 19 * 4;  // 98496 bytes
    cudaFuncSetAttribute(pass2, cudaFuncAttributeMaxDynamicSharedMemorySize, smem2);

    wtrans<<<10, 512>>>(wts);
    pass1<<<dim3(576, 8), 256>>>(x);
    pass2<<<dim3(12, 12, 16), 512, smem2>>>(alpha, bias, out);
}

// round 9
// speedup vs baseline: 1.2357x; 1.0487x over previous
#include <cuda_runtime.h>
#include <cstdint>
#include <cstddef>

// ============================================================================
// Compile-time basis construction
// ============================================================================
__host__ __device__ constexpr double cexp_(double v) {
    double t = 1.0, s = 1.0;
    for (int n = 1; n < 90; ++n) { t *= v / n; s += t; }
    return s;
}
__host__ __device__ constexpr double csqrt_(double v) {
    if (v <= 0.0) return 0.0;
    double x = v < 1.0 ? 1.0 : v;
    for (int i = 0; i < 80; ++i) x = 0.5 * (x + v / x);
    return x;
}

struct Basis {
    float b0[3][5][5];
    float br[3][2][5][5];
    float bi[3][2][5][5];
};

__host__ __device__ constexpr Basis make_basis() {
    Basis B{};
    for (int yy = 0; yy < 5; ++yy) {
        for (int xx = 0; xx < 5; ++xx) {
            double ys = yy - 2.0, xs = xx - 2.0;
            double r = csqrt_(ys * ys + xs * xs);
            double cth = r > 0.0 ? xs / r : 1.0;
            double sth = r > 0.0 ? ys / r : 0.0;
            double ring0 = cexp_(-(r - 0.0) * (r - 0.0) / 0.72);
            double ring1 = cexp_(-(r - 1.0) * (r - 1.0) / 0.72);
            double ring2 = cexp_(-(r - 2.0) * (r - 2.0) / 0.72);
            B.b0[0][yy][xx] = (float)ring0;
            B.b0[1][yy][xx] = (float)ring1;
            B.b0[2][yy][xx] = (float)ring2;
            double ck = cth, sk = sth;
            for (int k = 0; k < 3; ++k) {
                B.br[k][0][yy][xx] = (float)(ring1 * ck);
                B.br[k][1][yy][xx] = (float)(ring2 * ck);
                B.bi[k][0][yy][xx] = (float)(ring1 * sk);
                B.bi[k][1][yy][xx] = (float)(ring2 * sk);
                double cn = ck * cth - sk * sth;
                double sn = sk * cth + ck * sth;
                ck = cn; sk = sn;
            }
        }
    }
    return B;
}

#define FMA2(acc, a, b) \
    asm("fma.rn.f32x2 %0, %1, %2, %0;" : "+l"(acc) : "l"(a), "l"(b))
#define SPLAT2(dst, f) \
    asm("mov.b64 %0, {%1, %1};" : "=l"(dst) : "f"(f))

// ============================================================================
// Fused kernel: channel mix (phase B) + steered transpose-conv (phase C)
// entirely in shared memory. CTA = 16x16 input tile -> 32x32 output tile,
// one oh half (72 mixed channels). 1024 threads, 1 CTA/SM.
//
// smem: xs[32][360]  (18x18 tile, pitch 20)        46080 B
//       ysm[72][360] (mixed channels, pitch 20)   103680 B
//       ws[8][322]   (weights, channel-pair pad)   10304 B
// ============================================================================
__device__ __forceinline__ float dotT(const float (&T)[5][5],
                                      const float (&w)[3][3],
                                      int SY, int SX) {
    float s = 0.f;
#pragma unroll
    for (int dy = 0; dy < 3; ++dy) {
        if (dy < SY) continue;
        int vy = (SY ? 5 : 4) - 2 * dy;
#pragma unroll
        for (int dx = 0; dx < 3; ++dx) {
            if (dx < SX) continue;
            int vx = (SX ? 5 : 4) - 2 * dx;
            float cf = T[vy][vx];
            if (cf != 0.f) s += cf * w[dy][dx];
        }
    }
    return s;
}

__global__ __launch_bounds__(1024, 1) void fused(const float* __restrict__ x,
                                                 const float* __restrict__ wts,
                                                 const float* __restrict__ alpha,
                                                 const float* __restrict__ bias,
                                                 float* __restrict__ out) {
    constexpr Basis BAS = make_basis();
    extern __shared__ float sm[];
    float* xs  = sm;                    // [32][360]
    float* ysm = sm + 32 * 360;         // [72][360]
    float* ws  = sm + (32 + 72) * 360;  // [8][322]

    const int tx = blockIdx.x, ty = blockIdx.y;
    const int n  = blockIdx.z >> 1;
    const int oh = blockIdx.z & 1;
    const int tid = threadIdx.x;
    const int ix0 = tx * 16, iy0 = ty * 16;

    // ---- Phase A: stage weights (channel-paired, pitch 10) + x tile -------
    for (int e = tid; e < 2560; e += 1024) {
        int o = e / 320, r = e % 320, i = r / 10, c = r % 10;
        ws[o * 322 + i * 10 + c] =
            (c < 9) ? wts[(oh * 8 + o) * 288 + i * 9 + c] : 0.f;
    }
    const float* xg = x + (size_t)n * 32 * 36864;
    const bool interior = (tx > 0) & (tx < 11) & (ty > 0) & (ty < 11);
    if (interior) {
        for (int e = tid; e < 10368; e += 1024) {
            int i = e / 324, rem = e % 324, r = rem / 18, cc = rem % 18;
            xs[i * 360 + r * 20 + cc] =
                xg[(size_t)i * 36864 + (iy0 - 1 + r) * 192 + (ix0 - 1 + cc)];
        }
    } else {
        for (int e = tid; e < 10368; e += 1024) {
            int i = e / 324, rem = e % 324, r = rem / 18, cc = rem % 18;
            int gy = iy0 - 1 + r, gx = ix0 - 1 + cc;
            float v = 0.f;
            if ((unsigned)gy < 192u && (unsigned)gx < 192u)
                v = xg[(size_t)i * 36864 + gy * 192 + gx];
            xs[i * 360 + r * 20 + cc] = v;
        }
    }
    __syncthreads();

    // ---- Phase B: ysm[o1*9+c][px] = sum_i ws[o1][i][c] * xs[i][px] --------
    {
        const int o1 = tid & 7;
        const int pg = tid >> 3;     // 0..127, quads of 4 px; pg<90 active
        if (pg < 90) {
            const int px0 = pg * 4;
            unsigned long long acc2[5][4];
#pragma unroll
            for (int p = 0; p < 5; ++p)
#pragma unroll
                for (int j = 0; j < 4; ++j) acc2[p][j] = 0ULL;

            const float* xp = xs + px0;
            const float* wg = ws + o1 * 322;

#pragma unroll 4
            for (int i = 0; i < 32; ++i) {
                float4 xv = *(const float4*)(xp + i * 360);
                unsigned long long x0, x1, x2, x3;
                SPLAT2(x0, xv.x); SPLAT2(x1, xv.y);
                SPLAT2(x2, xv.z); SPLAT2(x3, xv.w);
                unsigned long long xa[4] = {x0, x1, x2, x3};
#pragma unroll
                for (int p = 0; p < 5; ++p) {
                    unsigned long long w2 =
                        *(const unsigned long long*)(wg + i * 10 + p * 2);
#pragma unroll
                    for (int j = 0; j < 4; ++j) FMA2(acc2[p][j], w2, xa[j]);
                }
            }

            float* yb = ysm + o1 * 9 * 360 + px0;
#pragma unroll
            for (int p = 0; p < 5; ++p) {
                float lo[4], hi[4];
#pragma unroll
                for (int j = 0; j < 4; ++j) {
                    uint2 u = *(uint2*)&acc2[p][j];
                    lo[j] = __uint_as_float(u.x);
                    hi[j] = __uint_as_float(u.y);
                }
                *(float4*)(yb + (size_t)(2 * p) * 360) =
                    make_float4(lo[0], lo[1], lo[2], lo[3]);
                if (p < 4)
                    *(float4*)(yb + (size_t)(2 * p + 1) * 360) =
                        make_float4(hi[0], hi[1], hi[2], hi[3]);
            }
        }
    }
    __syncthreads();

    // ---- Phase C: taps + modulation + rho/bias epilogue -------------------
    const int q  = tid & 255;
    const int os = tid >> 8;       // 0..3, 2 ol each
    const int qy = q >> 4, qx = q & 15;
    const int py0 = ty * 32 + 2 * qy;
    const int px0 = tx * 32 + 2 * qx;

    float C1[2][2], S1[2][2], RHO[2][2];
    {
        const float* a0p = alpha + (size_t)n * 147456 + (size_t)py0 * 384 + px0;
        const float* a1p = a0p + (size_t)8 * 147456;
#pragma unroll
        for (int sy = 0; sy < 2; ++sy)
#pragma unroll
            for (int sx = 0; sx < 2; ++sx) {
                float a0 = a0p[sy * 384 + sx];
                float a1 = a1p[sy * 384 + sx];
                float rho = sqrtf(a0 * a0 + a1 * a1);
                float inv = 1.0f / (rho + 1e-8f);
                RHO[sy][sx] = rho;
                C1[sy][sx] = a0 * inv;
                S1[sy][sx] = a1 * inv;
            }
    }

#pragma unroll
    for (int oi = 0; oi < 2; ++oi) {
        const int ol = os * 2 + oi;
        const int o  = oh * 8 + ol;
        float acc[2][2] = {{0.f, 0.f}, {0.f, 0.f}};
        float ck[2][2], sk[2][2];
#pragma unroll
        for (int sy = 0; sy < 2; ++sy)
#pragma unroll
            for (int sx = 0; sx < 2; ++sx) { ck[sy][sx] = C1[sy][sx]; sk[sy][sx] = S1[sy][sx]; }

#pragma unroll
        for (int c = 0; c < 9; ++c) {
            if (c == 5 || c == 7) {
#pragma unroll
                for (int sy = 0; sy < 2; ++sy)
#pragma unroll
                    for (int sx = 0; sx < 2; ++sx) {
                        float cn = ck[sy][sx] * C1[sy][sx] - sk[sy][sx] * S1[sy][sx];
                        float sn = sk[sy][sx] * C1[sy][sx] + ck[sy][sx] * S1[sy][sx];
                        ck[sy][sx] = cn; sk[sy][sx] = sn;
                    }
            }
            const float* wbp = ysm + (ol * 9 + c) * 360 + qy * 20 + qx;
            float w[3][3];
#pragma unroll
            for (int dy = 0; dy < 3; ++dy)
#pragma unroll
                for (int dx = 0; dx < 3; ++dx) w[dy][dx] = wbp[dy * 20 + dx];

            if (c < 3) {
                acc[0][0] += dotT(BAS.b0[c], w, 0, 0);
                acc[0][1] += dotT(BAS.b0[c], w, 0, 1);
                acc[1][0] += dotT(BAS.b0[c], w, 1, 0);
                acc[1][1] += dotT(BAS.b0[c], w, 1, 1);
            } else {
                const int k = (c - 3) >> 1;
                const int j = (c - 3) & 1;
#pragma unroll
                for (int sy = 0; sy < 2; ++sy)
#pragma unroll
                    for (int sx = 0; sx < 2; ++sx) {
                        float dR = dotT(BAS.br[k][j], w, sy, sx);
                        float dI = dotT(BAS.bi[k][j], w, sy, sx);
                        acc[sy][sx] += dR * ck[sy][sx] + dI * sk[sy][sx];
                    }
            }
        }
        float bo = bias[o];
#pragma unroll
        for (int sy = 0; sy < 2; ++sy) {
            float2 v;
            v.x = RHO[sy][0] * acc[sy][0] + bo;
            v.y = RHO[sy][1] * acc[sy][1] + bo;
            *(float2*)(out + ((size_t)(n * 16 + o)) * 147456 +
                       (size_t)(py0 + sy) * 384 + px0) = v;
        }
    }
}

// ============================================================================
// Launch
// ============================================================================
extern "C" void kernel_launch(void* const* d_in, const int* in_sizes, int n_in,
                              void* d_out, int out_size) {
    const float* x     = (const float*)d_in[0];  // (8,32,192,192)
    const float* alpha = (const float*)d_in[1];  // (2,8,1,384,384)
    const float* wts   = (const float*)d_in[2];  // (16,32,9)
    const float* bias  = (const float*)d_in[3];  // (16,)
    float* out = (float*)d_out;                  // (8,16,384,384)

    (void)in_sizes; (void)n_in; (void)out_size;

    const int smem = (32 * 360 + 72 * 360 + 8 * 322) * 4;  // 160064 bytes
    cudaFuncSetAttribute(fused, cudaFuncAttributeMaxDynamicSharedMemorySize, smem);

    fused<<<dim3(12, 12, 16), 1024, smem>>>(x, wts, alpha, bias, out);
}

// round 10
// speedup vs baseline: 1.2447x; 1.0073x over previous
#include <cuda_runtime.h>
#include <cstdint>
#include <cstddef>

// ============================================================================
// Compile-time basis construction
// ============================================================================
__host__ __device__ constexpr double cexp_(double v) {
    double t = 1.0, s = 1.0;
    for (int n = 1; n < 90; ++n) { t *= v / n; s += t; }
    return s;
}
__host__ __device__ constexpr double csqrt_(double v) {
    if (v <= 0.0) return 0.0;
    double x = v < 1.0 ? 1.0 : v;
    for (int i = 0; i < 80; ++i) x = 0.5 * (x + v / x);
    return x;
}

struct Basis {
    float b0[3][5][5];
    float br[3][2][5][5];
    float bi[3][2][5][5];
};

__host__ __device__ constexpr Basis make_basis() {
    Basis B{};
    for (int yy = 0; yy < 5; ++yy) {
        for (int xx = 0; xx < 5; ++xx) {
            double ys = yy - 2.0, xs = xx - 2.0;
            double r = csqrt_(ys * ys + xs * xs);
            double cth = r > 0.0 ? xs / r : 1.0;
            double sth = r > 0.0 ? ys / r : 0.0;
            double ring0 = cexp_(-(r - 0.0) * (r - 0.0) / 0.72);
            double ring1 = cexp_(-(r - 1.0) * (r - 1.0) / 0.72);
            double ring2 = cexp_(-(r - 2.0) * (r - 2.0) / 0.72);
            B.b0[0][yy][xx] = (float)ring0;
            B.b0[1][yy][xx] = (float)ring1;
            B.b0[2][yy][xx] = (float)ring2;
            double ck = cth, sk = sth;
            for (int k = 0; k < 3; ++k) {
                B.br[k][0][yy][xx] = (float)(ring1 * ck);
                B.br[k][1][yy][xx] = (float)(ring2 * ck);
                B.bi[k][0][yy][xx] = (float)(ring1 * sk);
                B.bi[k][1][yy][xx] = (float)(ring2 * sk);
                double cn = ck * cth - sk * sth;
                double sn = sk * cth + ck * sth;
                ck = cn; sk = sn;
            }
        }
    }
    return B;
}

#define FMA2(acc, a, b) \
    asm("fma.rn.f32x2 %0, %1, %2, %0;" : "+l"(acc) : "l"(a), "l"(b))
#define SPLAT2(dst, f) \
    asm("mov.b64 %0, {%1, %1};" : "=l"(dst) : "f"(f))

// ============================================================================
// Fused kernel: channel mix (phase B) + steered transpose-conv (phase C)
// entirely in shared memory. CTA = 16x16 input tile -> 32x32 output tile,
// one oh half (72 mixed channels). 1024 threads, 1 CTA/SM.
//
// smem: xs[32][360]  (18x18 tile, pitch 20)        46080 B
//       ysm[72][360] (mixed channels, pitch 20)   103680 B
//       ws[8][322]   (weights, channel-pair pad)   10304 B
// ============================================================================
__device__ __forceinline__ float dotT(const float (&T)[5][5],
                                      const float (&w)[3][3],
                                      int SY, int SX) {
    float s = 0.f;
#pragma unroll
    for (int dy = 0; dy < 3; ++dy) {
        if (dy < SY) continue;
        int vy = (SY ? 5 : 4) - 2 * dy;
#pragma unroll
        for (int dx = 0; dx < 3; ++dx) {
            if (dx < SX) continue;
            int vx = (SX ? 5 : 4) - 2 * dx;
            float cf = T[vy][vx];
            if (cf != 0.f) s += cf * w[dy][dx];
        }
    }
    return s;
}

__global__ __launch_bounds__(1024, 1) void fused(const float* __restrict__ x,
                                                 const float* __restrict__ wts,
                                                 const float* __restrict__ alpha,
                                                 const float* __restrict__ bias,
                                                 float* __restrict__ out) {
    constexpr Basis BAS = make_basis();
    extern __shared__ float sm[];
    float* xs  = sm;                    // [32][360]
    float* ysm = sm + 32 * 360;         // [72][360]
    float* ws  = sm + (32 + 72) * 360;  // [8][322]

    const int tx = blockIdx.x, ty = blockIdx.y;
    const int n  = blockIdx.z >> 1;
    const int oh = blockIdx.z & 1;
    const int tid = threadIdx.x;
    const int ix0 = tx * 16, iy0 = ty * 16;

    // ---- Phase A: stage weights (channel-paired, pitch 10) + x tile -------
    for (int e = tid; e < 2560; e += 1024) {
        int o = e / 320, r = e % 320, i = r / 10, c = r % 10;
        ws[o * 322 + i * 10 + c] =
            (c < 9) ? wts[(oh * 8 + o) * 288 + i * 9 + c] : 0.f;
    }
    const float* xg = x + (size_t)n * 32 * 36864;
    const bool interior = (tx > 0) & (tx < 11) & (ty > 0) & (ty < 11);
    if (interior) {
        for (int e = tid; e < 10368; e += 1024) {
            int i = e / 324, rem = e % 324, r = rem / 18, cc = rem % 18;
            xs[i * 360 + r * 20 + cc] =
                xg[(size_t)i * 36864 + (iy0 - 1 + r) * 192 + (ix0 - 1 + cc)];
        }
    } else {
        for (int e = tid; e < 10368; e += 1024) {
            int i = e / 324, rem = e % 324, r = rem / 18, cc = rem % 18;
            int gy = iy0 - 1 + r, gx = ix0 - 1 + cc;
            float v = 0.f;
            if ((unsigned)gy < 192u && (unsigned)gx < 192u)
                v = xg[(size_t)i * 36864 + gy * 192 + gx];
            xs[i * 360 + r * 20 + cc] = v;
        }
    }
    __syncthreads();

    // ---- Phase B: ysm[o1*9+c][px] = sum_i ws[o1][i][c] * xs[i][px] --------
    {
        const int o1 = tid & 7;
        const int pg = tid >> 3;     // 0..127, quads of 4 px; pg<90 active
        if (pg < 90) {
            const int px0 = pg * 4;
            unsigned long long acc2[5][4];
#pragma unroll
            for (int p = 0; p < 5; ++p)
#pragma unroll
                for (int j = 0; j < 4; ++j) acc2[p][j] = 0ULL;

            const float* xp = xs + px0;
            const float* wg = ws + o1 * 322;

#pragma unroll 4
            for (int i = 0; i < 32; ++i) {
                float4 xv = *(const float4*)(xp + i * 360);
                unsigned long long x0, x1, x2, x3;
                SPLAT2(x0, xv.x); SPLAT2(x1, xv.y);
                SPLAT2(x2, xv.z); SPLAT2(x3, xv.w);
                unsigned long long xa[4] = {x0, x1, x2, x3};
#pragma unroll
                for (int p = 0; p < 5; ++p) {
                    unsigned long long w2 =
                        *(const unsigned long long*)(wg + i * 10 + p * 2);
#pragma unroll
                    for (int j = 0; j < 4; ++j) FMA2(acc2[p][j], w2, xa[j]);
                }
            }

            float* yb = ysm + o1 * 9 * 360 + px0;
#pragma unroll
            for (int p = 0; p < 5; ++p) {
                float lo[4], hi[4];
#pragma unroll
                for (int j = 0; j < 4; ++j) {
                    uint2 u = *(uint2*)&acc2[p][j];
                    lo[j] = __uint_as_float(u.x);
                    hi[j] = __uint_as_float(u.y);
                }
                *(float4*)(yb + (size_t)(2 * p) * 360) =
                    make_float4(lo[0], lo[1], lo[2], lo[3]);
                if (p < 4)
                    *(float4*)(yb + (size_t)(2 * p + 1) * 360) =
                        make_float4(hi[0], hi[1], hi[2], hi[3]);
            }
        }
    }
    __syncthreads();

    // ---- Phase C: taps + modulation + rho/bias epilogue -------------------
    const int q  = tid & 255;
    const int os = tid >> 8;       // 0..3, 2 ol each
    const int qy = q >> 4, qx = q & 15;
    const int py0 = ty * 32 + 2 * qy;
    const int px0 = tx * 32 + 2 * qx;

    float C1[2][2], S1[2][2], RHO[2][2];
    {
        const float* a0p = alpha + (size_t)n * 147456 + (size_t)py0 * 384 + px0;
        const float* a1p = a0p + (size_t)8 * 147456;
#pragma unroll
        for (int sy = 0; sy < 2; ++sy)
#pragma unroll
            for (int sx = 0; sx < 2; ++sx) {
                float a0 = a0p[sy * 384 + sx];
                float a1 = a1p[sy * 384 + sx];
                float rho = sqrtf(a0 * a0 + a1 * a1);
                float inv = 1.0f / (rho + 1e-8f);
                RHO[sy][sx] = rho;
                C1[sy][sx] = a0 * inv;
                S1[sy][sx] = a1 * inv;
            }
    }

#pragma unroll
    for (int oi = 0; oi < 2; ++oi) {
        const int ol = os * 2 + oi;
        const int o  = oh * 8 + ol;
        float acc[2][2] = {{0.f, 0.f}, {0.f, 0.f}};
        float ck[2][2], sk[2][2];
#pragma unroll
        for (int sy = 0; sy < 2; ++sy)
#pragma unroll
            for (int sx = 0; sx < 2; ++sx) { ck[sy][sx] = C1[sy][sx]; sk[sy][sx] = S1[sy][sx]; }

#pragma unroll
        for (int c = 0; c < 9; ++c) {
            if (c == 5 || c == 7) {
#pragma unroll
                for (int sy = 0; sy < 2; ++sy)
#pragma unroll
                    for (int sx = 0; sx < 2; ++sx) {
                        float cn = ck[sy][sx] * C1[sy][sx] - sk[sy][sx] * S1[sy][sx];
                        float sn = sk[sy][sx] * C1[sy][sx] + ck[sy][sx] * S1[sy][sx];
                        ck[sy][sx] = cn; sk[sy][sx] = sn;
                    }
            }
            const float* wbp = ysm + (ol * 9 + c) * 360 + qy * 20 + qx;
            float w[3][3];
#pragma unroll
            for (int dy = 0; dy < 3; ++dy)
#pragma unroll
                for (int dx = 0; dx < 3; ++dx) w[dy][dx] = wbp[dy * 20 + dx];

            if (c < 3) {
                acc[0][0] += dotT(BAS.b0[c], w, 0, 0);
                acc[0][1] += dotT(BAS.b0[c], w, 0, 1);
                acc[1][0] += dotT(BAS.b0[c], w, 1, 0);
                acc[1][1] += dotT(BAS.b0[c], w, 1, 1);
            } else {
                const int k = (c - 3) >> 1;
                const int j = (c - 3) & 1;
#pragma unroll
                for (int sy = 0; sy < 2; ++sy)
#pragma unroll
                    for (int sx = 0; sx < 2; ++sx) {
                        float dR = dotT(BAS.br[k][j], w, sy, sx);
                        float dI = dotT(BAS.bi[k][j], w, sy, sx);
                        acc[sy][sx] += dR * ck[sy][sx] + dI * sk[sy][sx];
                    }
            }
        }
        float bo = bias[o];
#pragma unroll
        for (int sy = 0; sy < 2; ++sy) {
            float2 v;
            v.x = RHO[sy][0] * acc[sy][0] + bo;
            v.y = RHO[sy][1] * acc[sy][1] + bo;
            *(float2*)(out + ((size_t)(n * 16 + o)) * 147456 +
                       (size_t)(py0 + sy) * 384 + px0) = v;
        }
    }
}

// ============================================================================
// Launch
// ============================================================================
extern "C" void kernel_launch(void* const* d_in, const int* in_sizes, int n_in,
                              void* d_out, int out_size) {
    const float* x     = (const float*)d_in[0];  // (8,32,192,192)
    const float* alpha = (const float*)d_in[1];  // (2,8,1,384,384)
    const float* wts   = (const float*)d_in[2];  // (16,32,9)
    const float* bias  = (const float*)d_in[3];  // (16,)
    float* out = (float*)d_out;                  // (8,16,384,384)

    (void)in_sizes; (void)n_in; (void)out_size;

    const int smem = (32 * 360 + 72 * 360 + 8 * 322) * 4;  // 160064 bytes
    cudaFuncSetAttribute(fused, cudaFuncAttributeMaxDynamicSharedMemorySize, smem);

    fused<<<dim3(12, 12, 16), 1024, smem>>>(x, wts, alpha, bias, out);
}